// round 11
// baseline (speedup 1.0000x reference)
#include <cuda_runtime.h>
#include <cuda_bf16.h>
#include <math.h>
#include <stdint.h>

#define BB 32
#define NN 577
#define DD 384
#define LL 12
#define NRPT 4
#define HH 1536
#define MMAX 580
#define MPAD 640

// ---------------- scratch (static device arrays; no allocation) ----------------
__device__ float g_x[BB * NN * DD];
__device__ float g_q[BB * NN * DD];      // q GEMM out; reused for prod out
__device__ float g_k[BB * MMAX * DD];
__device__ float g_scores[(size_t)BB * NN * MPAD];
__device__ float g_hist[NRPT * BB * DD];
// int8 operand buffers
__device__ uint8_t g_mem8[BB * MMAX * DD];
__device__ uint8_t g_xn8[BB * NN * DD];
__device__ uint8_t g_q8[BB * NN * DD];
__device__ uint8_t g_k8[BB * MMAX * DD];
__device__ uint8_t g_vT8[BB * DD * MPAD];
__device__ uint8_t g_attn8[(size_t)BB * NN * MPAD];
__device__ uint8_t g_pn8[BB * NN * DD];
__device__ uint8_t g_h8[(size_t)BB * NN * HH];
__device__ uint8_t g_wqkv8[LL * 3 * DD * DD];
__device__ uint8_t g_wproj8[LL * DD * DD];
__device__ uint8_t g_wfc18[LL * HH * DD];
__device__ uint8_t g_wfc28[LL * DD * HH];

// operand scales (int8 fixed-point: match dynamic range of each tensor)
#define SC_W 1024.0f    // weights sigma ~0.02 -> 4sig*1024 ~ 82
#define SC_LN 24.0f     // LN outputs sigma ~1
#define SC_MEM 24.0f    // residual stream sigma ~1
#define SC_ATTN 127.0f  // softmax probs in [0,1]
#define SC_V 48.0f      // v sigma ~0.4
#define SC_H 64.0f      // gelu(fc1) range ~±1.6

// ---------------- PTX helpers ----------------
__device__ __forceinline__ uint32_t smem_u32(const void* p) {
    uint32_t a;
    asm("{ .reg .u64 t; cvta.to.shared.u64 t, %1; cvt.u32.u64 %0, t; }" : "=r"(a) : "l"(p));
    return a;
}
__device__ __forceinline__ void cpasync16(uint32_t dst, const void* src, int srcsize) {
    asm volatile("cp.async.cg.shared.global [%0], [%1], 16, %2;" :: "r"(dst), "l"(src), "r"(srcsize));
}
__device__ __forceinline__ void cpcommit() { asm volatile("cp.async.commit_group;" ::: "memory"); }
__device__ __forceinline__ void cpwait1() { asm volatile("cp.async.wait_group 1;" ::: "memory"); }
__device__ __forceinline__ void cpwait0() { asm volatile("cp.async.wait_group 0;" ::: "memory"); }

// pack two floats -> 2x s8 (round-to-nearest, clamp to ±127)
__device__ __forceinline__ uint16_t pack_s8(float lo, float hi) {
    int a = __float2int_rn(fminf(fmaxf(lo, -127.f), 127.f));
    int b = __float2int_rn(fminf(fmaxf(hi, -127.f), 127.f));
    return (uint16_t)((a & 0xff) | ((b & 0xff) << 8));
}

#define LDSM4(r0, r1, r2, r3, a)                                                     \
    asm volatile("ldmatrix.sync.aligned.m8n8.x4.shared.b16 {%0,%1,%2,%3}, [%4];"     \
                 : "=r"(r0), "=r"(r1), "=r"(r2), "=r"(r3) : "r"(a))

#define MMAS8(d, av, bv)                                                             \
    asm volatile("mma.sync.aligned.m16n8k32.row.col.s32.s8.s8.s32 "                  \
                 "{%0,%1,%2,%3},{%4,%5,%6,%7},{%8,%9},{%0,%1,%2,%3};"                \
                 : "+r"((d)[0]), "+r"((d)[1]), "+r"((d)[2]), "+r"((d)[3])            \
                 : "r"((av)[0]), "r"((av)[1]), "r"((av)[2]), "r"((av)[3]),           \
                   "r"((bv)[0]), "r"((bv)[1]))

// smem: 3 stages x (A[128][128]s8 16KB + B[128][128]s8 16KB)
#define SM_A(s) ((s) * 32768)
#define SM_B(s) ((s) * 32768 + 16384)
#define SMEM_DYN (3 * 32768 + 1024)

__device__ __forceinline__ float gelu_exact(float v) {
    return 0.5f * v * (1.0f + erff(v * 0.70710678118654752f));
}

// ---------------- INT8 IMMA GEMM: C[M,*] = A[M,K](s8) @ W[N,K]^T(s8) + epilogue -------
// 256 threads = 8 warps (4 x 2). Tile 128x128, K-chunk 128, 3-stage cp.async ring.
// All modes: base = (float)acc*alpha + bias
// mode 0: f32 out, bias[gn] (may be null; odd Nvalid allowed iff null)
// mode 1: s8 out, v = gelu(base)*oscale          (Nvalid % 128 == 0)
// mode 2: f32 out, v = base*ls[gn] + res[..]     (Nvalid % 128 == 0)
// mode 3: s8 out, v = base*oscale, bias[gm]; zero-fill cols [Nvalid, Npad) (Npad even)
__global__ void __launch_bounds__(256, 2)
mma_gemm_nt(const uint8_t* __restrict__ A, const uint8_t* __restrict__ W,
            const float* __restrict__ bias, const float* __restrict__ ls,
            const float* __restrict__ res, void* __restrict__ Cv,
            int Mrows, int Nvalid, int Npad, int K, int lda, int ldw, int ldc,
            long zA, long zW, long zC, float alpha, float oscale, int mode) {
    extern __shared__ char smraw[];
    uint32_t sbase = (smem_u32(smraw) + 1023u) & ~1023u;
    int tid = threadIdx.x, wid = tid >> 5, lid = tid & 31;
    int bz = blockIdx.z;
    A += (size_t)bz * zA;
    W += (size_t)bz * zW;
    const float* resp = res ? res + (size_t)bz * zC : (const float*)0;
    int m0 = blockIdx.y * 128, n0 = blockIdx.x * 128;

    int wm = wid & 3;   // row group: wm*32
    int wn = wid >> 2;  // col group: wn*64

    int acc[2][8][4];
#pragma unroll
    for (int a = 0; a < 2; a++)
#pragma unroll
        for (int b = 0; b < 8; b++)
#pragma unroll
            for (int c = 0; c < 4; c++) acc[a][b][c] = 0;

    int nk = K >> 7;   // K-chunk = 128 s8 = 128 B/row

#define LOAD_CHUNK(kc, s) do {                                                         \
    int _k0 = (kc) << 7;                                                               \
    _Pragma("unroll")                                                                  \
    for (int _i = 0; _i < 4; _i++) {                                                   \
        int _idx = tid + 256 * _i;                                                     \
        int _row = _idx >> 3, _g = _idx & 7;                                           \
        int _gm = m0 + _row;                                                           \
        int _pr = (_gm < Mrows) ? 16 : 0;                                              \
        const uint8_t* _src = A + (size_t)(_pr ? _gm : 0) * lda + _k0 + _g * 16;       \
        cpasync16(sbase + SM_A(s) + _row * 128 + (((_g ^ (_row & 7))) << 4), _src, _pr); \
    }                                                                                  \
    _Pragma("unroll")                                                                  \
    for (int _i = 0; _i < 4; _i++) {                                                   \
        int _idx = tid + 256 * _i;                                                     \
        int _row = _idx >> 3, _g = _idx & 7;                                           \
        int _gn = n0 + _row;                                                           \
        int _pr = (_gn < Nvalid) ? 16 : 0;                                             \
        const uint8_t* _src = W + (size_t)(_pr ? _gn : 0) * ldw + _k0 + _g * 16;       \
        cpasync16(sbase + SM_B(s) + _row * 128 + (((_g ^ (_row & 7))) << 4), _src, _pr); \
    }                                                                                  \
    cpcommit();                                                                        \
} while (0)

    LOAD_CHUNK(0, 0);
    if (nk > 1) LOAD_CHUNK(1, 1);

    int grp = lid >> 3, rin = lid & 7;
    int slot = 0;
    for (int i = 0; i < nk; i++) {
        if (i + 1 < nk) cpwait1(); else cpwait0();
        __syncthreads();
        if (i + 2 < nk) {
            int ns = slot + 2; if (ns >= 3) ns -= 3;
            LOAD_CHUNK(i + 2, ns);
        }
        int s = slot;
#pragma unroll
        for (int ks = 0; ks < 4; ks++) {   // each ks = 32 s8 of K (2 granules of 16B)
            uint32_t af[2][4], bf[8][2];
#pragma unroll
            for (int mt = 0; mt < 2; mt++) {
                int row = wm * 32 + mt * 16 + rin + (grp & 1) * 8;
                int kg = ks * 2 + (grp >> 1);
                uint32_t ad = sbase + SM_A(s) + row * 128 + ((kg ^ (row & 7)) << 4);
                LDSM4(af[mt][0], af[mt][1], af[mt][2], af[mt][3], ad);
            }
#pragma unroll
            for (int np = 0; np < 4; np++) {
                int row = wn * 64 + np * 16 + rin + (grp >> 1) * 8;
                int kg = ks * 2 + (grp & 1);
                uint32_t ad = sbase + SM_B(s) + row * 128 + ((kg ^ (row & 7)) << 4);
                LDSM4(bf[2 * np][0], bf[2 * np][1], bf[2 * np + 1][0], bf[2 * np + 1][1], ad);
            }
#pragma unroll
            for (int mt = 0; mt < 2; mt++)
#pragma unroll
                for (int nt = 0; nt < 8; nt++)
                    MMAS8(acc[mt][nt], af[mt], bf[nt]);
        }
        slot++; if (slot >= 3) slot = 0;
    }

    // ------------- vectorized epilogue -------------
#pragma unroll
    for (int mt = 0; mt < 2; mt++) {
        int rbase = m0 + wm * 32 + mt * 16 + (lid >> 2);
#pragma unroll
        for (int nt = 0; nt < 8; nt++) {
            int c0 = n0 + wn * 64 + nt * 8 + (lid & 3) * 2;
#pragma unroll
            for (int half = 0; half < 2; half++) {
                int gm = rbase + half * 8;
                if (gm >= Mrows) continue;
                float a0 = __int2float_rn(acc[mt][nt][half * 2]) * alpha;
                float a1 = __int2float_rn(acc[mt][nt][half * 2 + 1]) * alpha;
                if (mode == 0) {
                    float* C = (float*)Cv + (size_t)bz * zC;
                    if (bias) {
                        float2 v = make_float2(a0 + bias[c0], a1 + bias[c0 + 1]);
                        *(float2*)(C + (size_t)gm * ldc + c0) = v;
                    } else {
                        if (c0 + 1 < Nvalid) {
                            *(float2*)(C + (size_t)gm * ldc + c0) = make_float2(a0, a1);
                        } else if (c0 < Nvalid) {
                            C[(size_t)gm * ldc + c0] = a0;
                        }
                    }
                } else if (mode == 1) {
                    uint8_t* C = (uint8_t*)Cv + (size_t)bz * zC;
                    float v0 = gelu_exact(a0 + bias[c0]) * oscale;
                    float v1 = gelu_exact(a1 + bias[c0 + 1]) * oscale;
                    *(uint16_t*)(C + (size_t)gm * ldc + c0) = pack_s8(v0, v1);
                } else if (mode == 2) {
                    float* C = (float*)Cv + (size_t)bz * zC;
                    float2 r = *(const float2*)(resp + (size_t)gm * ldc + c0);
                    float2 v = make_float2((a0 + bias[c0]) * ls[c0] + r.x,
                                           (a1 + bias[c0 + 1]) * ls[c0 + 1] + r.y);
                    *(float2*)(C + (size_t)gm * ldc + c0) = v;
                } else {
                    uint8_t* C = (uint8_t*)Cv + (size_t)bz * zC;
                    float bb = bias ? bias[gm] : 0.f;
                    float v0 = (c0 < Nvalid) ? (a0 + bb) * oscale : 0.f;
                    float v1 = (c0 + 1 < Nvalid) ? (a1 + bb) * oscale : 0.f;
                    if (c0 + 1 < Npad)
                        *(uint16_t*)(C + (size_t)gm * ldc + c0) = pack_s8(v0, v1);
                }
            }
        }
    }
}

// ---------------- small kernels ----------------
__global__ void copy_kernel(float* __restrict__ dst, const float* __restrict__ src, int n) {
    int i = blockIdx.x * 256 + threadIdx.x;
    if (i < n) dst[i] = src[i];
}
// fp32 -> s8 (x SC_W), pairs
__global__ void cvt_w8_kernel(uint8_t* __restrict__ dst, const float* __restrict__ src, int npair) {
    int i = blockIdx.x * 256 + threadIdx.x;
    if (i >= npair) return;
    float2 v = *(const float2*)(src + 2 * i);
    *(uint16_t*)(dst + 2 * i) = pack_s8(v.x * SC_W, v.y * SC_W);
}
__global__ void save_cls_kernel(const float* __restrict__ x, float* __restrict__ hist_r) {
    int i = blockIdx.x * 256 + threadIdx.x;
    if (i >= BB * DD) return;
    int b = i / DD, d = i % DD;
    hist_r[i] = x[(size_t)b * NN * DD + d];
}
__global__ void restore_patches_kernel(float* __restrict__ x, const float* __restrict__ x_in) {
    int i = blockIdx.x * 256 + threadIdx.x;
    if (i >= BB * NN * DD) return;
    int tok = (i / DD) % NN;
    if (tok != 0) x[i] = x_in[i];
}
// mem (f32 gather) -> s8 x SC_MEM, pair-per-thread
__global__ void build_mem8_kernel(uint8_t* __restrict__ mem, const float* __restrict__ x,
                                  const float* __restrict__ hist, int Mk) {
    int i = blockIdx.x * 256 + threadIdx.x;   // pair index
    int npair = BB * Mk * (DD / 2);
    if (i >= npair) return;
    int d2 = i % (DD / 2);
    int t = (i / (DD / 2)) % Mk;
    int b = i / ((DD / 2) * Mk);
    const float* src;
    if (t < NN) src = x + ((size_t)b * NN + t) * DD + 2 * d2;
    else        src = hist + ((size_t)(t - NN) * BB + b) * DD + 2 * d2;
    float2 v = *(const float2*)src;
    *(uint16_t*)(mem + ((size_t)b * Mk + t) * DD + 2 * d2) = pack_s8(v.x * SC_MEM, v.y * SC_MEM);
}

// layernorm f32 in -> s8 out (x SC_LN), 1 warp per row
__global__ void ln_s8_kernel(const float* __restrict__ in, uint8_t* __restrict__ out,
                             const float* __restrict__ w, const float* __restrict__ b, int rows) {
    int row = blockIdx.x * 8 + (threadIdx.x >> 5);
    int lane = threadIdx.x & 31;
    if (row >= rows) return;
    const float2* p = (const float2*)(in + (size_t)row * DD);
    float2 v[6];
    float s = 0.f;
#pragma unroll
    for (int i = 0; i < 6; i++) { v[i] = p[lane + 32 * i]; s += v[i].x + v[i].y; }
#pragma unroll
    for (int o = 16; o; o >>= 1) s += __shfl_xor_sync(0xffffffffu, s, o);
    float mu = s * (1.0f / DD);
    float var = 0.f;
#pragma unroll
    for (int i = 0; i < 6; i++) {
        float dx = v[i].x - mu, dy = v[i].y - mu;
        var += dx * dx + dy * dy;
    }
#pragma unroll
    for (int o = 16; o; o >>= 1) var += __shfl_xor_sync(0xffffffffu, var, o);
    float inv = rsqrtf(var * (1.0f / DD) + 1e-6f);
    uint8_t* q = out + (size_t)row * DD;
    const float2* w2 = (const float2*)w;
    const float2* b2 = (const float2*)b;
#pragma unroll
    for (int i = 0; i < 6; i++) {
        int c = lane + 32 * i;
        float2 ww = w2[c], bb = b2[c];
        float o0 = ((v[i].x - mu) * inv * ww.x + bb.x) * SC_LN;
        float o1 = ((v[i].y - mu) * inv * ww.y + bb.y) * SC_LN;
        *(uint16_t*)(q + 2 * c) = pack_s8(o0, o1);
    }
}

// softmax: f32 in (stride MPAD) -> s8 out x SC_ATTN (stride MPAD, zero-padded), 1 warp/row
__global__ void softmax_s8_kernel(const float* __restrict__ s, uint8_t* __restrict__ out,
                                  int rows, int Mk) {
    int row = blockIdx.x * 8 + (threadIdx.x >> 5);
    int lane = threadIdx.x & 31;
    if (row >= rows) return;
    const float2* p = (const float2*)(s + (size_t)row * MPAD);
    float2 v[10];
    float mx = -1e30f;
#pragma unroll
    for (int i = 0; i < 10; i++) {
        int j = 2 * (lane + 32 * i);
        float2 t = p[lane + 32 * i];
        v[i].x = (j < Mk) ? t.x : -1e30f;
        v[i].y = (j + 1 < Mk) ? t.y : -1e30f;
        mx = fmaxf(mx, fmaxf(v[i].x, v[i].y));
    }
#pragma unroll
    for (int o = 16; o; o >>= 1) mx = fmaxf(mx, __shfl_xor_sync(0xffffffffu, mx, o));
    float sum = 0.f;
#pragma unroll
    for (int i = 0; i < 10; i++) {
        v[i].x = __expf(v[i].x - mx);
        v[i].y = __expf(v[i].y - mx);
        sum += v[i].x + v[i].y;
    }
#pragma unroll
    for (int o = 16; o; o >>= 1) sum += __shfl_xor_sync(0xffffffffu, sum, o);
    float r = SC_ATTN / sum;
    uint8_t* q = out + (size_t)row * MPAD;
#pragma unroll
    for (int i = 0; i < 10; i++) {
        int j = 2 * (lane + 32 * i);
        float o0 = (j < Mk) ? v[i].x * r : 0.f;
        float o1 = (j + 1 < Mk) ? v[i].y * r : 0.f;
        *(uint16_t*)(q + j) = pack_s8(o0, o1);
    }
}

// ---------------- host orchestration ----------------
static inline int ceil_div(int a, int b) { return (a + b - 1) / b; }

extern "C" void kernel_launch(void* const* d_in, const int* in_sizes, int n_in,
                              void* d_out, int out_size) {
    const float* x_in    = (const float*)d_in[0];
    const float* norm1_w = (const float*)d_in[1];
    const float* norm1_b = (const float*)d_in[2];
    const float* qkv_w   = (const float*)d_in[3];
    const float* qkv_b   = (const float*)d_in[4];
    const float* qn_w    = (const float*)d_in[5];
    const float* qn_b    = (const float*)d_in[6];
    const float* kn_w    = (const float*)d_in[7];
    const float* kn_b    = (const float*)d_in[8];
    const float* an_w    = (const float*)d_in[9];
    const float* an_b    = (const float*)d_in[10];
    const float* proj_w  = (const float*)d_in[11];
    const float* proj_b  = (const float*)d_in[12];
    const float* ls1     = (const float*)d_in[13];
    const float* norm2_w = (const float*)d_in[14];
    const float* norm2_b = (const float*)d_in[15];
    const float* fc1_w   = (const float*)d_in[16];
    const float* fc1_b   = (const float*)d_in[17];
    const float* fc2_w   = (const float*)d_in[18];
    const float* fc2_b   = (const float*)d_in[19];
    const float* ls2     = (const float*)d_in[20];
    float* out = (float*)d_out;

    cudaFuncSetAttribute(mma_gemm_nt, cudaFuncAttributeMaxDynamicSharedMemorySize, SMEM_DYN);

    float *px, *pq, *pk, *pscores, *phist;
    uint8_t *pmem, *pxn, *pq8, *pk8, *pvT, *pattn, *ppn, *ph;
    uint8_t *wqkv, *wproj, *wfc1, *wfc2;
    cudaGetSymbolAddress((void**)&px, g_x);
    cudaGetSymbolAddress((void**)&pq, g_q);
    cudaGetSymbolAddress((void**)&pk, g_k);
    cudaGetSymbolAddress((void**)&pscores, g_scores);
    cudaGetSymbolAddress((void**)&phist, g_hist);
    cudaGetSymbolAddress((void**)&pmem, g_mem8);
    cudaGetSymbolAddress((void**)&pxn, g_xn8);
    cudaGetSymbolAddress((void**)&pq8, g_q8);
    cudaGetSymbolAddress((void**)&pk8, g_k8);
    cudaGetSymbolAddress((void**)&pvT, g_vT8);
    cudaGetSymbolAddress((void**)&pattn, g_attn8);
    cudaGetSymbolAddress((void**)&ppn, g_pn8);
    cudaGetSymbolAddress((void**)&ph, g_h8);
    cudaGetSymbolAddress((void**)&wqkv, g_wqkv8);
    cudaGetSymbolAddress((void**)&wproj, g_wproj8);
    cudaGetSymbolAddress((void**)&wfc1, g_wfc18);
    cudaGetSymbolAddress((void**)&wfc2, g_wfc28);

    const float scale = 1.0f / sqrtf((float)DD);
    const int nXND = BB * NN * DD;
    const int rowsX = BB * NN;

    // epilogue alphas (undo operand scaling)
    const float aQK    = 1.0f / (SC_LN * SC_W);
    const float aMEMW  = 1.0f / (SC_MEM * SC_W);
    const float aSC    = scale / (SC_LN * SC_LN);
    const float aPV    = 1.0f / (SC_ATTN * SC_V);
    const float aFC1   = 1.0f / (SC_LN * SC_W);
    const float aFC2   = 1.0f / (SC_H * SC_W);

    // weight conversions (fp32 -> s8 x SC_W)
    {
        int n1 = LL * 3 * DD * DD / 2;
        cvt_w8_kernel<<<ceil_div(n1, 256), 256>>>(wqkv, qkv_w, n1);
        int n2 = LL * DD * DD / 2;
        cvt_w8_kernel<<<ceil_div(n2, 256), 256>>>(wproj, proj_w, n2);
        int n3 = LL * HH * DD / 2;
        cvt_w8_kernel<<<ceil_div(n3, 256), 256>>>(wfc1, fc1_w, n3);
        cvt_w8_kernel<<<ceil_div(n3, 256), 256>>>(wfc2, fc2_w, n3);
    }

    copy_kernel<<<ceil_div(nXND, 256), 256>>>(px, x_in, nXND);

    for (int r = 0; r < NRPT; r++) {
        int Mk = NN + r;
        int rowsM = BB * Mk;

        save_cls_kernel<<<ceil_div(BB * DD, 256), 256>>>(px, phist + (size_t)r * BB * DD);
        restore_patches_kernel<<<ceil_div(nXND, 256), 256>>>(px, x_in);
        build_mem8_kernel<<<ceil_div(BB * Mk * DD / 2, 256), 256>>>(pmem, px, phist, Mk);

        int mtX = ceil_div(rowsX, 128);
        int mtM = ceil_div(rowsM, 128);
        int ntMk = ceil_div(Mk, 128);

        for (int l = 0; l < LL; l++) {
            const uint8_t* Wq = wqkv + (size_t)l * 3 * DD * DD;
            const uint8_t* Wk = Wq + (size_t)DD * DD;
            const uint8_t* Wv = Wq + (size_t)2 * DD * DD;
            const float* bq = qkv_b + (size_t)l * 3 * DD;
            const float* bk = bq + DD;
            const float* bv = bq + 2 * DD;

            // norm1 -> xn (s8 x SC_LN)
            ln_s8_kernel<<<ceil_div(rowsX, 8), 256>>>(px, pxn, norm1_w + l * DD, norm1_b + l * DD, rowsX);

            // q = xn @ Wq^T + bq  (f32)
            mma_gemm_nt<<<dim3(3, mtX, 1), 256, SMEM_DYN>>>(
                pxn, Wq, bq, 0, 0, pq, rowsX, DD, DD, DD, DD, DD, DD, 0, 0, 0, aQK, 1.f, 0);
            // k = mem @ Wk^T + bk (f32)
            mma_gemm_nt<<<dim3(3, mtM, 1), 256, SMEM_DYN>>>(
                pmem, Wk, bk, 0, 0, pk, rowsM, DD, DD, DD, DD, DD, DD, 0, 0, 0, aMEMW, 1.f, 0);
            // vT = Wv @ mem^T + bv(row) -> s8 x SC_V [D, MPAD] per batch, pad zeros
            mma_gemm_nt<<<dim3(MPAD / 128, 3, BB), 256, SMEM_DYN>>>(
                Wv, pmem, bv, 0, 0, pvT, DD, Mk, MPAD, DD, DD, DD, MPAD,
                0, (long)Mk * DD, (long)DD * MPAD, aMEMW, SC_V, 3);

            // q/k layernorms -> s8
            ln_s8_kernel<<<ceil_div(rowsX, 8), 256>>>(pq, pq8, qn_w + l * DD, qn_b + l * DD, rowsX);
            ln_s8_kernel<<<ceil_div(rowsM, 8), 256>>>(pk, pk8, kn_w + l * DD, kn_b + l * DD, rowsM);

            // scores = scale * q @ k^T  (f32, per batch, ldc=MPAD)
            mma_gemm_nt<<<dim3(ntMk, ceil_div(NN, 128), BB), 256, SMEM_DYN>>>(
                pq8, pk8, 0, 0, 0, pscores, NN, Mk, Mk, DD, DD, DD, MPAD,
                (long)NN * DD, (long)Mk * DD, (long)NN * MPAD, aSC, 1.f, 0);
            softmax_s8_kernel<<<ceil_div(BB * NN, 8), 256>>>(pscores, pattn, BB * NN, Mk);

            // prod = attn @ vT^T  (f32, per batch; K = MPAD zero-padded)
            mma_gemm_nt<<<dim3(3, ceil_div(NN, 128), BB), 256, SMEM_DYN>>>(
                pattn, pvT, 0, 0, 0, pq, NN, DD, DD, MPAD, MPAD, MPAD, DD,
                (long)NN * MPAD, (long)DD * MPAD, (long)NN * DD, aPV, 1.f, 0);

            // attn-out layernorm -> s8
            ln_s8_kernel<<<ceil_div(rowsX, 8), 256>>>(pq, ppn, an_w + l * DD, an_b + l * DD, rowsX);

            // x += (prodn @ Wproj^T + bias) * ls1
            mma_gemm_nt<<<dim3(3, mtX, 1), 256, SMEM_DYN>>>(
                ppn, wproj + (size_t)l * DD * DD, proj_b + l * DD, ls1 + l * DD, px, px,
                rowsX, DD, DD, DD, DD, DD, DD, 0, 0, 0, aQK, 1.f, 2);

            // MLP
            ln_s8_kernel<<<ceil_div(rowsX, 8), 256>>>(px, pxn, norm2_w + l * DD, norm2_b + l * DD, rowsX);
            mma_gemm_nt<<<dim3(HH / 128, mtX, 1), 256, SMEM_DYN>>>(
                pxn, wfc1 + (size_t)l * HH * DD, fc1_b + l * HH, 0, 0, ph,
                rowsX, HH, HH, DD, DD, DD, HH, 0, 0, 0, aFC1, SC_H, 1);
            mma_gemm_nt<<<dim3(3, mtX, 1), 256, SMEM_DYN>>>(
                ph, wfc2 + (size_t)l * DD * HH, fc2_b + l * DD, ls2 + l * DD, px, px,
                rowsX, DD, DD, HH, HH, HH, DD, 0, 0, 0, aFC2, 1.f, 2);
        }
    }

    copy_kernel<<<ceil_div(nXND, 256), 256>>>(out, px, nXND);
}

// round 12
// speedup vs baseline: 2.8294x; 2.8294x over previous
#include <cuda_runtime.h>
#include <cuda_bf16.h>
#include <math.h>
#include <stdint.h>

#define BB 32
#define NN 577
#define DD 384
#define LL 12
#define NRPT 4
#define HH 1536
#define MMAX 580
#define MPAD 640

// ---------------- scratch ----------------
__device__ float g_x[BB * NN * DD];
__device__ float g_hist[NRPT * BB * DD];
__device__ uint8_t g_mem8[BB * MMAX * DD];
__device__ uint8_t g_xn8[BB * NN * DD];
__device__ uint8_t g_q8[BB * NN * DD];
__device__ uint8_t g_k8[BB * MMAX * DD];
__device__ uint8_t g_vT8[BB * DD * MPAD];
__device__ uint8_t g_attn8[(size_t)BB * NN * MPAD];
__device__ uint8_t g_pn8[BB * NN * DD];
__device__ uint8_t g_h8[(size_t)BB * NN * HH];
__device__ uint8_t g_wqkv8[LL * 3 * DD * DD];
__device__ uint8_t g_wproj8[LL * DD * DD];
__device__ uint8_t g_wfc18[LL * HH * DD];
__device__ uint8_t g_wfc28[LL * DD * HH];

// fp8 operand scales (powers of 2)
#define SC_W 32.0f
#define SC_LN 4.0f
#define SC_MEM 4.0f
#define SC_ATTN 16.0f
#define SC_V 8.0f
#define SC_H 16.0f

// ---------------- PTX helpers ----------------
__device__ __forceinline__ uint32_t smem_u32(const void* p) {
    uint32_t a;
    asm("{ .reg .u64 t; cvta.to.shared.u64 t, %1; cvt.u32.u64 %0, t; }" : "=r"(a) : "l"(p));
    return a;
}
__device__ __forceinline__ void cpasync16(uint32_t dst, const void* src, int srcsize) {
    asm volatile("cp.async.cg.shared.global [%0], [%1], 16, %2;" :: "r"(dst), "l"(src), "r"(srcsize));
}
__device__ __forceinline__ void cpcommit() { asm volatile("cp.async.commit_group;" ::: "memory"); }
__device__ __forceinline__ void cpwait1() { asm volatile("cp.async.wait_group 1;" ::: "memory"); }
__device__ __forceinline__ void cpwait0() { asm volatile("cp.async.wait_group 0;" ::: "memory"); }

__device__ __forceinline__ uint16_t pack_e4m3(float lo, float hi) {
    uint16_t r;
    asm("cvt.rn.satfinite.e4m3x2.f32 %0, %1, %2;" : "=h"(r) : "f"(hi), "f"(lo));
    return r;
}

#define LDSM4(r0, r1, r2, r3, a)                                                     \
    asm volatile("ldmatrix.sync.aligned.m8n8.x4.shared.b16 {%0,%1,%2,%3}, [%4];"     \
                 : "=r"(r0), "=r"(r1), "=r"(r2), "=r"(r3) : "r"(a))

#define MMAFP8(d, av, bv)                                                            \
    asm volatile("mma.sync.aligned.m16n8k32.row.col.f32.e4m3.e4m3.f32 "              \
                 "{%0,%1,%2,%3},{%4,%5,%6,%7},{%8,%9},{%0,%1,%2,%3};"                \
                 : "+f"((d)[0]), "+f"((d)[1]), "+f"((d)[2]), "+f"((d)[3])            \
                 : "r"((av)[0]), "r"((av)[1]), "r"((av)[2]), "r"((av)[3]),           \
                   "r"((bv)[0]), "r"((bv)[1]))

__device__ __forceinline__ float gelu_exact(float v) {
    return 0.5f * v * (1.0f + erff(v * 0.70710678118654752f));
}

// ============ kernel 1: generic 128x128 GEMM (used for vT and fc1 only) ============
#define SM_A(s) ((s) * 32768)
#define SM_B(s) ((s) * 32768 + 16384)
#define SMEM_G (3 * 32768 + 1024)

// mode 1: fp8 out, v = gelu(acc*alpha + bias[gn])*oscale   (Nvalid % 128 == 0)
// mode 3: fp8 out, v = (acc*alpha + bias[gm])*oscale; zero-fill cols [Nvalid, Npad)
__global__ void __launch_bounds__(256, 2)
mma_gemm_nt(const uint8_t* __restrict__ A, const uint8_t* __restrict__ W,
            const float* __restrict__ bias, void* __restrict__ Cv,
            int Mrows, int Nvalid, int Npad, int K, int lda, int ldw, int ldc,
            long zA, long zW, long zC, float alpha, float oscale, int mode) {
    extern __shared__ char smraw[];
    uint32_t sbase = (smem_u32(smraw) + 1023u) & ~1023u;
    int tid = threadIdx.x, wid = tid >> 5, lid = tid & 31;
    int bz = blockIdx.z;
    A += (size_t)bz * zA;
    W += (size_t)bz * zW;
    int m0 = blockIdx.y * 128, n0 = blockIdx.x * 128;
    int wm = wid & 3, wn = wid >> 2;

    float acc[2][8][4];
#pragma unroll
    for (int a = 0; a < 2; a++)
#pragma unroll
        for (int b = 0; b < 8; b++)
#pragma unroll
            for (int c = 0; c < 4; c++) acc[a][b][c] = 0.f;

    int nk = K >> 7;

#define LOADC_G(kc, s) do {                                                            \
    int _k0 = (kc) << 7;                                                               \
    _Pragma("unroll")                                                                  \
    for (int _i = 0; _i < 4; _i++) {                                                   \
        int _idx = tid + 256 * _i;                                                     \
        int _row = _idx >> 3, _g = _idx & 7;                                           \
        int _gm = m0 + _row;                                                           \
        int _pr = (_gm < Mrows) ? 16 : 0;                                              \
        const uint8_t* _src = A + (size_t)(_pr ? _gm : 0) * lda + _k0 + _g * 16;       \
        cpasync16(sbase + SM_A(s) + _row * 128 + (((_g ^ (_row & 7))) << 4), _src, _pr); \
    }                                                                                  \
    _Pragma("unroll")                                                                  \
    for (int _i = 0; _i < 4; _i++) {                                                   \
        int _idx = tid + 256 * _i;                                                     \
        int _row = _idx >> 3, _g = _idx & 7;                                           \
        int _gn = n0 + _row;                                                           \
        int _pr = (_gn < Nvalid) ? 16 : 0;                                             \
        const uint8_t* _src = W + (size_t)(_pr ? _gn : 0) * ldw + _k0 + _g * 16;       \
        cpasync16(sbase + SM_B(s) + _row * 128 + (((_g ^ (_row & 7))) << 4), _src, _pr); \
    }                                                                                  \
    cpcommit();                                                                        \
} while (0)

    LOADC_G(0, 0);
    if (nk > 1) LOADC_G(1, 1);
    int grp = lid >> 3, rin = lid & 7;
    int slot = 0;
    for (int i = 0; i < nk; i++) {
        if (i + 1 < nk) cpwait1(); else cpwait0();
        __syncthreads();
        if (i + 2 < nk) {
            int ns = slot + 2; if (ns >= 3) ns -= 3;
            LOADC_G(i + 2, ns);
        }
        int s = slot;
#pragma unroll
        for (int ks = 0; ks < 4; ks++) {
            uint32_t af[2][4], bf[8][2];
#pragma unroll
            for (int mt = 0; mt < 2; mt++) {
                int row = wm * 32 + mt * 16 + rin + (grp & 1) * 8;
                int kg = ks * 2 + (grp >> 1);
                uint32_t ad = sbase + SM_A(s) + row * 128 + ((kg ^ (row & 7)) << 4);
                LDSM4(af[mt][0], af[mt][1], af[mt][2], af[mt][3], ad);
            }
#pragma unroll
            for (int np = 0; np < 4; np++) {
                int row = wn * 64 + np * 16 + rin + (grp >> 1) * 8;
                int kg = ks * 2 + (grp & 1);
                uint32_t ad = sbase + SM_B(s) + row * 128 + ((kg ^ (row & 7)) << 4);
                LDSM4(bf[2 * np][0], bf[2 * np][1], bf[2 * np + 1][0], bf[2 * np + 1][1], ad);
            }
#pragma unroll
            for (int mt = 0; mt < 2; mt++)
#pragma unroll
                for (int nt = 0; nt < 8; nt++)
                    MMAFP8(acc[mt][nt], af[mt], bf[nt]);
        }
        slot++; if (slot >= 3) slot = 0;
    }

#pragma unroll
    for (int mt = 0; mt < 2; mt++) {
        int rbase = m0 + wm * 32 + mt * 16 + (lid >> 2);
#pragma unroll
        for (int nt = 0; nt < 8; nt++) {
            int c0 = n0 + wn * 64 + nt * 8 + (lid & 3) * 2;
#pragma unroll
            for (int half = 0; half < 2; half++) {
                int gm = rbase + half * 8;
                if (gm >= Mrows) continue;
                float a0 = acc[mt][nt][half * 2] * alpha;
                float a1 = acc[mt][nt][half * 2 + 1] * alpha;
                uint8_t* C = (uint8_t*)Cv + (size_t)bz * zC;
                if (mode == 1) {
                    float v0 = gelu_exact(a0 + bias[c0]) * oscale;
                    float v1 = gelu_exact(a1 + bias[c0 + 1]) * oscale;
                    *(uint16_t*)(C + (size_t)gm * ldc + c0) = pack_e4m3(v0, v1);
                } else {
                    float bb = bias ? bias[gm] : 0.f;
                    float v0 = (c0 < Nvalid) ? (a0 + bb) * oscale : 0.f;
                    float v1 = (c0 + 1 < Nvalid) ? (a1 + bb) * oscale : 0.f;
                    if (c0 + 1 < Npad)
                        *(uint16_t*)(C + (size_t)gm * ldc + c0) = pack_e4m3(v0, v1);
                }
            }
        }
    }
}

// ============ kernel 2: 64x384 GEMM + fused LayerNorm epilogue -> e4m3 ============
// warps: 2 row groups (wm) x 4 col groups (wn, 96 cols = 12 n-tiles)
// mode 0: base = acc*alpha (+bias[c]);  out8 = LN(base)*SC_LN
// mode 1: t = (acc*alpha + bias[c])*ls[c] + res[gm*384+c]; xout=t (f32); out8 = LN(t)*SC_LN
#define LN_STG 57344              // 8KB A + 48KB B per stage
#define LN_SA(s) ((s) * LN_STG)
#define LN_SB(s) ((s) * LN_STG + 8192)
#define LN_RED (3 * LN_STG)       // 64 rows x 4 warpcols x float2 = 2KB
#define SMEM_LN (3 * LN_STG + 2048 + 1024)

__global__ void __launch_bounds__(256, 1)
gemm_ln_f8(const uint8_t* __restrict__ A, const uint8_t* __restrict__ W,
           const float* __restrict__ bias, const float* __restrict__ ls,
           const float* __restrict__ res, const float* __restrict__ lnw,
           const float* __restrict__ lnb, uint8_t* __restrict__ out8,
           float* __restrict__ xout, int Mrows, int K, int lda, int ldw,
           long zA, long zW, long zOut, float alpha, int mode) {
    extern __shared__ char smraw[];
    uint32_t sbase = (smem_u32(smraw) + 1023u) & ~1023u;
    char* salc = smraw + (sbase - smem_u32(smraw));
    float2* red = (float2*)(salc + LN_RED);   // [64][4]
    int tid = threadIdx.x, wid = tid >> 5, lid = tid & 31;
    int bz = blockIdx.z;
    A += (size_t)bz * zA;
    W += (size_t)bz * zW;
    out8 += (size_t)bz * zOut;
    int m0 = blockIdx.y * 64;
    int wm = wid & 1, wn = wid >> 1;

    float acc[2][12][4];
#pragma unroll
    for (int a = 0; a < 2; a++)
#pragma unroll
        for (int b = 0; b < 12; b++)
#pragma unroll
            for (int c = 0; c < 4; c++) acc[a][b][c] = 0.f;

    int nk = K >> 7;

#define LOADC_L(kc, s) do {                                                            \
    int _k0 = (kc) << 7;                                                               \
    _Pragma("unroll")                                                                  \
    for (int _i = 0; _i < 2; _i++) {                                                   \
        int _idx = tid + 256 * _i;                                                     \
        int _row = _idx >> 3, _g = _idx & 7;                                           \
        int _gm = m0 + _row;                                                           \
        int _pr = (_gm < Mrows) ? 16 : 0;                                              \
        const uint8_t* _src = A + (size_t)(_pr ? _gm : 0) * lda + _k0 + _g * 16;       \
        cpasync16(sbase + LN_SA(s) + _row * 128 + (((_g ^ (_row & 7))) << 4), _src, _pr); \
    }                                                                                  \
    _Pragma("unroll")                                                                  \
    for (int _i = 0; _i < 12; _i++) {                                                  \
        int _idx = tid + 256 * _i;                                                     \
        int _row = _idx >> 3, _g = _idx & 7;                                           \
        const uint8_t* _src = W + (size_t)_row * ldw + _k0 + _g * 16;                  \
        cpasync16(sbase + LN_SB(s) + _row * 128 + (((_g ^ (_row & 7))) << 4), _src, 16); \
    }                                                                                  \
    cpcommit();                                                                        \
} while (0)

    LOADC_L(0, 0);
    if (nk > 1) LOADC_L(1, 1);
    int grp = lid >> 3, rin = lid & 7;
    int slot = 0;
    for (int i = 0; i < nk; i++) {
        if (i + 1 < nk) cpwait1(); else cpwait0();
        __syncthreads();
        if (i + 2 < nk) {
            int ns = slot + 2; if (ns >= 3) ns -= 3;
            LOADC_L(i + 2, ns);
        }
        int s = slot;
#pragma unroll
        for (int ks = 0; ks < 4; ks++) {
            uint32_t af[2][4], bf[12][2];
#pragma unroll
            for (int mt = 0; mt < 2; mt++) {
                int row = wm * 32 + mt * 16 + rin + (grp & 1) * 8;
                int kg = ks * 2 + (grp >> 1);
                uint32_t ad = sbase + LN_SA(s) + row * 128 + ((kg ^ (row & 7)) << 4);
                LDSM4(af[mt][0], af[mt][1], af[mt][2], af[mt][3], ad);
            }
#pragma unroll
            for (int np = 0; np < 6; np++) {
                int row = wn * 96 + np * 16 + rin + (grp >> 1) * 8;
                int kg = ks * 2 + (grp & 1);
                uint32_t ad = sbase + LN_SB(s) + row * 128 + ((kg ^ (row & 7)) << 4);
                LDSM4(bf[2 * np][0], bf[2 * np][1], bf[2 * np + 1][0], bf[2 * np + 1][1], ad);
            }
#pragma unroll
            for (int mt = 0; mt < 2; mt++)
#pragma unroll
                for (int nt = 0; nt < 12; nt++)
                    MMAFP8(acc[mt][nt], af[mt], bf[nt]);
        }
        slot++; if (slot >= 3) slot = 0;
    }

    // ---- epilogue: transform in place, then row LayerNorm ----
    const float2* bias2 = (const float2*)bias;
    const float2* ls2p = (const float2*)ls;
    const float2* lw2 = (const float2*)lnw;
    const float2* lb2 = (const float2*)lnb;

#pragma unroll
    for (int mt = 0; mt < 2; mt++) {
#pragma unroll
        for (int half = 0; half < 2; half++) {
            int rl = wm * 32 + mt * 16 + (lid >> 2) + half * 8;
            int gm = m0 + rl;
            int gmr = gm < Mrows ? gm : (Mrows - 1);
            float s = 0.f, s2 = 0.f;
#pragma unroll
            for (int nt = 0; nt < 12; nt++) {
                int c = wn * 96 + nt * 8 + (lid & 3) * 2;
                float a0 = acc[mt][nt][half * 2] * alpha;
                float a1 = acc[mt][nt][half * 2 + 1] * alpha;
                if (bias) { float2 bb = bias2[c >> 1]; a0 += bb.x; a1 += bb.y; }
                if (mode == 1) {
                    float2 l2 = ls2p[c >> 1];
                    float2 r2 = *(const float2*)(res + (size_t)gmr * DD + c);
                    a0 = a0 * l2.x + r2.x;
                    a1 = a1 * l2.y + r2.y;
                    if (gm < Mrows)
                        *(float2*)(xout + (size_t)gm * DD + c) = make_float2(a0, a1);
                }
                acc[mt][nt][half * 2] = a0;
                acc[mt][nt][half * 2 + 1] = a1;
                s += a0 + a1;
                s2 += a0 * a0 + a1 * a1;
            }
#pragma unroll
            for (int o = 1; o <= 2; o <<= 1) {
                s += __shfl_xor_sync(0xffffffffu, s, o);
                s2 += __shfl_xor_sync(0xffffffffu, s2, o);
            }
            if ((lid & 3) == 0) red[rl * 4 + wn] = make_float2(s, s2);
        }
    }
    __syncthreads();
#pragma unroll
    for (int mt = 0; mt < 2; mt++) {
#pragma unroll
        for (int half = 0; half < 2; half++) {
            int rl = wm * 32 + mt * 16 + (lid >> 2) + half * 8;
            int gm = m0 + rl;
            float s = 0.f, s2 = 0.f;
#pragma unroll
            for (int j = 0; j < 4; j++) {
                float2 p = red[rl * 4 + j];
                s += p.x; s2 += p.y;
            }
            float mu = s * (1.0f / DD);
            float var = s2 * (1.0f / DD) - mu * mu;
            float inv = rsqrtf(fmaxf(var, 0.f) + 1e-6f);
            if (gm < Mrows) {
#pragma unroll
                for (int nt = 0; nt < 12; nt++) {
                    int c = wn * 96 + nt * 8 + (lid & 3) * 2;
                    float2 w2 = lw2[c >> 1], b2 = lb2[c >> 1];
                    float o0 = ((acc[mt][nt][half * 2] - mu) * inv * w2.x + b2.x) * SC_LN;
                    float o1 = ((acc[mt][nt][half * 2 + 1] - mu) * inv * w2.y + b2.y) * SC_LN;
                    *(uint16_t*)(out8 + (size_t)gm * DD + c) = pack_e4m3(o0, o1);
                }
            }
        }
    }
}

// ============ kernel 3: scores (32 x 640) + fused masked softmax -> e4m3 ============
// warps: 1 row group x 8 col groups (80 cols = 10 n-tiles each)
#define SMS_STG 86016             // 4KB A + 80KB B per stage (2 stages)
#define SMS_SA(s) ((s) * SMS_STG)
#define SMS_SB(s) ((s) * SMS_STG + 4096)
#define SMS_MX (2 * SMS_STG)
#define SMS_SUM (2 * SMS_STG + 1024)
#define SMEM_SM (2 * SMS_STG + 2048 + 1024)

__global__ void __launch_bounds__(256, 1)
gemm_sm_f8(const uint8_t* __restrict__ Q, const uint8_t* __restrict__ Kp,
           uint8_t* __restrict__ attn, int Mk, float alpha) {
    extern __shared__ char smraw[];
    uint32_t sbase = (smem_u32(smraw) + 1023u) & ~1023u;
    char* salc = smraw + (sbase - smem_u32(smraw));
    float* mxbuf = (float*)(salc + SMS_MX);    // [32][8]
    float* sumbuf = (float*)(salc + SMS_SUM);  // [32][8]
    int tid = threadIdx.x, wid = tid >> 5, lid = tid & 31;
    int bz = blockIdx.z;
    const uint8_t* A = Q + (size_t)bz * NN * DD;
    const uint8_t* W = Kp + (size_t)bz * Mk * DD;
    uint8_t* out = attn + (size_t)bz * NN * MPAD;
    int m0 = blockIdx.y * 32;
    int wn = wid;

    float acc[2][10][4];
#pragma unroll
    for (int a = 0; a < 2; a++)
#pragma unroll
        for (int b = 0; b < 10; b++)
#pragma unroll
            for (int c = 0; c < 4; c++) acc[a][b][c] = 0.f;

#define LOADC_S(kc, s) do {                                                            \
    int _k0 = (kc) << 7;                                                               \
    {                                                                                  \
        int _row = tid >> 3, _g = tid & 7;                                             \
        int _gm = m0 + _row;                                                           \
        int _pr = (_gm < NN) ? 16 : 0;                                                 \
        const uint8_t* _src = A + (size_t)(_pr ? _gm : 0) * DD + _k0 + _g * 16;        \
        cpasync16(sbase + SMS_SA(s) + _row * 128 + (((_g ^ (_row & 7))) << 4), _src, _pr); \
    }                                                                                  \
    _Pragma("unroll")                                                                  \
    for (int _i = 0; _i < 20; _i++) {                                                  \
        int _idx = tid + 256 * _i;                                                     \
        int _row = _idx >> 3, _g = _idx & 7;                                           \
        int _pr = (_row < Mk) ? 16 : 0;                                                \
        const uint8_t* _src = W + (size_t)(_pr ? _row : 0) * DD + _k0 + _g * 16;       \
        cpasync16(sbase + SMS_SB(s) + _row * 128 + (((_g ^ (_row & 7))) << 4), _src, _pr); \
    }                                                                                  \
    cpcommit();                                                                        \
} while (0)

    LOADC_S(0, 0);
    LOADC_S(1, 1);
    int grp = lid >> 3, rin = lid & 7;
    for (int i = 0; i < 3; i++) {   // K = 384 -> nk = 3
        if (i + 1 < 3) cpwait1(); else cpwait0();
        __syncthreads();
        int s = i & 1;
#pragma unroll
        for (int ks = 0; ks < 4; ks++) {
            uint32_t af[2][4], bf[10][2];
#pragma unroll
            for (int mt = 0; mt < 2; mt++) {
                int row = mt * 16 + rin + (grp & 1) * 8;
                int kg = ks * 2 + (grp >> 1);
                uint32_t ad = sbase + SMS_SA(s) + row * 128 + ((kg ^ (row & 7)) << 4);
                LDSM4(af[mt][0], af[mt][1], af[mt][2], af[mt][3], ad);
            }
#pragma unroll
            for (int np = 0; np < 5; np++) {
                int row = wn * 80 + np * 16 + rin + (grp >> 1) * 8;
                int kg = ks * 2 + (grp & 1);
                uint32_t ad = sbase + SMS_SB(s) + row * 128 + ((kg ^ (row & 7)) << 4);
                LDSM4(bf[2 * np][0], bf[2 * np][1], bf[2 * np + 1][0], bf[2 * np + 1][1], ad);
            }
#pragma unroll
            for (int mt = 0; mt < 2; mt++)
#pragma unroll
                for (int nt = 0; nt < 10; nt++)
                    MMAFP8(acc[mt][nt], af[mt], bf[nt]);
        }
        if (i + 2 < 3) {
            __syncthreads();
            LOADC_S(i + 2, s);
        }
    }

    // ---- fused masked softmax ----
    // pass 1: scale + mask, row max
#pragma unroll
    for (int mt = 0; mt < 2; mt++) {
#pragma unroll
        for (int half = 0; half < 2; half++) {
            int rl = mt * 16 + (lid >> 2) + half * 8;
            float mx = -1e30f;
#pragma unroll
            for (int nt = 0; nt < 10; nt++) {
                int c = wn * 80 + nt * 8 + (lid & 3) * 2;
                float a0 = (c < Mk) ? acc[mt][nt][half * 2] * alpha : -1e30f;
                float a1 = (c + 1 < Mk) ? acc[mt][nt][half * 2 + 1] * alpha : -1e30f;
                acc[mt][nt][half * 2] = a0;
                acc[mt][nt][half * 2 + 1] = a1;
                mx = fmaxf(mx, fmaxf(a0, a1));
            }
#pragma unroll
            for (int o = 1; o <= 2; o <<= 1)
                mx = fmaxf(mx, __shfl_xor_sync(0xffffffffu, mx, o));
            if ((lid & 3) == 0) mxbuf[rl * 8 + wn] = mx;
        }
    }
    __syncthreads();
    // pass 2: exp + row sum
#pragma unroll
    for (int mt = 0; mt < 2; mt++) {
#pragma unroll
        for (int half = 0; half < 2; half++) {
            int rl = mt * 16 + (lid >> 2) + half * 8;
            float mx = -1e30f;
#pragma unroll
            for (int j = 0; j < 8; j++) mx = fmaxf(mx, mxbuf[rl * 8 + j]);
            float sum = 0.f;
#pragma unroll
            for (int nt = 0; nt < 10; nt++) {
                int c = wn * 80 + nt * 8 + (lid & 3) * 2;
                float e0 = (c < Mk) ? __expf(acc[mt][nt][half * 2] - mx) : 0.f;
                float e1 = (c + 1 < Mk) ? __expf(acc[mt][nt][half * 2 + 1] - mx) : 0.f;
                acc[mt][nt][half * 2] = e0;
                acc[mt][nt][half * 2 + 1] = e1;
                sum += e0 + e1;
            }
#pragma unroll
            for (int o = 1; o <= 2; o <<= 1)
                sum += __shfl_xor_sync(0xffffffffu, sum, o);
            if ((lid & 3) == 0) sumbuf[rl * 8 + wn] = sum;
        }
    }
    __syncthreads();
    // pass 3: normalize, quantize, store
#pragma unroll
    for (int mt = 0; mt < 2; mt++) {
#pragma unroll
        for (int half = 0; half < 2; half++) {
            int rl = mt * 16 + (lid >> 2) + half * 8;
            int gm = m0 + rl;
            float sum = 0.f;
#pragma unroll
            for (int j = 0; j < 8; j++) sum += sumbuf[rl * 8 + j];
            float rs = SC_ATTN / sum;
            if (gm < NN) {
#pragma unroll
                for (int nt = 0; nt < 10; nt++) {
                    int c = wn * 80 + nt * 8 + (lid & 3) * 2;
                    float o0 = acc[mt][nt][half * 2] * rs;
                    float o1 = acc[mt][nt][half * 2 + 1] * rs;
                    *(uint16_t*)(out + (size_t)gm * MPAD + c) = pack_e4m3(o0, o1);
                }
            }
        }
    }
}

// ---------------- small kernels ----------------
__global__ void copy_kernel(float* __restrict__ dst, const float* __restrict__ src, int n) {
    int i = blockIdx.x * 256 + threadIdx.x;
    if (i < n) dst[i] = src[i];
}
__global__ void cvt_w8_kernel(uint8_t* __restrict__ dst, const float* __restrict__ src, int npair) {
    int i = blockIdx.x * 256 + threadIdx.x;
    if (i >= npair) return;
    float2 v = *(const float2*)(src + 2 * i);
    *(uint16_t*)(dst + 2 * i) = pack_e4m3(v.x * SC_W, v.y * SC_W);
}
__global__ void save_cls_kernel(const float* __restrict__ x, float* __restrict__ hist_r) {
    int i = blockIdx.x * 256 + threadIdx.x;
    if (i >= BB * DD) return;
    int b = i / DD, d = i % DD;
    hist_r[i] = x[(size_t)b * NN * DD + d];
}
__global__ void restore_patches_kernel(float* __restrict__ x, const float* __restrict__ x_in) {
    int i = blockIdx.x * 256 + threadIdx.x;
    if (i >= BB * NN * DD) return;
    int tok = (i / DD) % NN;
    if (tok != 0) x[i] = x_in[i];
}
__global__ void build_mem8_kernel(uint8_t* __restrict__ mem, const float* __restrict__ x,
                                  const float* __restrict__ hist, int Mk) {
    int i = blockIdx.x * 256 + threadIdx.x;
    int npair = BB * Mk * (DD / 2);
    if (i >= npair) return;
    int d2 = i % (DD / 2);
    int t = (i / (DD / 2)) % Mk;
    int b = i / ((DD / 2) * Mk);
    const float* src;
    if (t < NN) src = x + ((size_t)b * NN + t) * DD + 2 * d2;
    else        src = hist + ((size_t)(t - NN) * BB + b) * DD + 2 * d2;
    float2 v = *(const float2*)src;
    *(uint16_t*)(mem + ((size_t)b * Mk + t) * DD + 2 * d2) = pack_e4m3(v.x * SC_MEM, v.y * SC_MEM);
}
// layernorm f32 -> e4m3 x SC_LN, 1 warp/row (repeat-start only)
__global__ void ln_f8_kernel(const float* __restrict__ in, uint8_t* __restrict__ out,
                             const float* __restrict__ w, const float* __restrict__ b, int rows) {
    int row = blockIdx.x * 8 + (threadIdx.x >> 5);
    int lane = threadIdx.x & 31;
    if (row >= rows) return;
    const float2* p = (const float2*)(in + (size_t)row * DD);
    float2 v[6];
    float s = 0.f;
#pragma unroll
    for (int i = 0; i < 6; i++) { v[i] = p[lane + 32 * i]; s += v[i].x + v[i].y; }
#pragma unroll
    for (int o = 16; o; o >>= 1) s += __shfl_xor_sync(0xffffffffu, s, o);
    float mu = s * (1.0f / DD);
    float var = 0.f;
#pragma unroll
    for (int i = 0; i < 6; i++) {
        float dx = v[i].x - mu, dy = v[i].y - mu;
        var += dx * dx + dy * dy;
    }
#pragma unroll
    for (int o = 16; o; o >>= 1) var += __shfl_xor_sync(0xffffffffu, var, o);
    float inv = rsqrtf(var * (1.0f / DD) + 1e-6f);
    uint8_t* q = out + (size_t)row * DD;
    const float2* w2 = (const float2*)w;
    const float2* b2 = (const float2*)b;
#pragma unroll
    for (int i = 0; i < 6; i++) {
        int c = lane + 32 * i;
        float2 ww = w2[c], bb = b2[c];
        float o0 = ((v[i].x - mu) * inv * ww.x + bb.x) * SC_LN;
        float o1 = ((v[i].y - mu) * inv * ww.y + bb.y) * SC_LN;
        *(uint16_t*)(q + 2 * c) = pack_e4m3(o0, o1);
    }
}

// ---------------- host orchestration ----------------
static inline int ceil_div(int a, int b) { return (a + b - 1) / b; }

extern "C" void kernel_launch(void* const* d_in, const int* in_sizes, int n_in,
                              void* d_out, int out_size) {
    const float* x_in    = (const float*)d_in[0];
    const float* norm1_w = (const float*)d_in[1];
    const float* norm1_b = (const float*)d_in[2];
    const float* qkv_w   = (const float*)d_in[3];
    const float* qkv_b   = (const float*)d_in[4];
    const float* qn_w    = (const float*)d_in[5];
    const float* qn_b    = (const float*)d_in[6];
    const float* kn_w    = (const float*)d_in[7];
    const float* kn_b    = (const float*)d_in[8];
    const float* an_w    = (const float*)d_in[9];
    const float* an_b    = (const float*)d_in[10];
    const float* proj_w  = (const float*)d_in[11];
    const float* proj_b  = (const float*)d_in[12];
    const float* ls1     = (const float*)d_in[13];
    const float* norm2_w = (const float*)d_in[14];
    const float* norm2_b = (const float*)d_in[15];
    const float* fc1_w   = (const float*)d_in[16];
    const float* fc1_b   = (const float*)d_in[17];
    const float* fc2_w   = (const float*)d_in[18];
    const float* fc2_b   = (const float*)d_in[19];
    const float* ls2     = (const float*)d_in[20];
    float* out = (float*)d_out;

    cudaFuncSetAttribute(mma_gemm_nt, cudaFuncAttributeMaxDynamicSharedMemorySize, SMEM_G);
    cudaFuncSetAttribute(gemm_ln_f8, cudaFuncAttributeMaxDynamicSharedMemorySize, SMEM_LN);
    cudaFuncSetAttribute(gemm_sm_f8, cudaFuncAttributeMaxDynamicSharedMemorySize, SMEM_SM);

    float *px, *phist;
    uint8_t *pmem, *pxn, *pq8, *pk8, *pvT, *pattn, *ppn, *ph;
    uint8_t *wqkv, *wproj, *wfc1, *wfc2;
    cudaGetSymbolAddress((void**)&px, g_x);
    cudaGetSymbolAddress((void**)&phist, g_hist);
    cudaGetSymbolAddress((void**)&pmem, g_mem8);
    cudaGetSymbolAddress((void**)&pxn, g_xn8);
    cudaGetSymbolAddress((void**)&pq8, g_q8);
    cudaGetSymbolAddress((void**)&pk8, g_k8);
    cudaGetSymbolAddress((void**)&pvT, g_vT8);
    cudaGetSymbolAddress((void**)&pattn, g_attn8);
    cudaGetSymbolAddress((void**)&ppn, g_pn8);
    cudaGetSymbolAddress((void**)&ph, g_h8);
    cudaGetSymbolAddress((void**)&wqkv, g_wqkv8);
    cudaGetSymbolAddress((void**)&wproj, g_wproj8);
    cudaGetSymbolAddress((void**)&wfc1, g_wfc18);
    cudaGetSymbolAddress((void**)&wfc2, g_wfc28);

    const float scale = 1.0f / sqrtf((float)DD);
    const int nXND = BB * NN * DD;
    const int rowsX = BB * NN;

    const float aQK   = 1.0f / (SC_LN * SC_W);
    const float aMEMW = 1.0f / (SC_MEM * SC_W);
    const float aSC   = scale / (SC_LN * SC_LN);
    const float aPV   = 1.0f / (SC_ATTN * SC_V);
    const float aFC1  = 1.0f / (SC_LN * SC_W);
    const float aFC2  = 1.0f / (SC_H * SC_W);

    {
        int n1 = LL * 3 * DD * DD / 2;
        cvt_w8_kernel<<<ceil_div(n1, 256), 256>>>(wqkv, qkv_w, n1);
        int n2 = LL * DD * DD / 2;
        cvt_w8_kernel<<<ceil_div(n2, 256), 256>>>(wproj, proj_w, n2);
        int n3 = LL * HH * DD / 2;
        cvt_w8_kernel<<<ceil_div(n3, 256), 256>>>(wfc1, fc1_w, n3);
        cvt_w8_kernel<<<ceil_div(n3, 256), 256>>>(wfc2, fc2_w, n3);
    }

    copy_kernel<<<ceil_div(nXND, 256), 256>>>(px, x_in, nXND);

    int mtX64 = ceil_div(rowsX, 64);          // 289

    for (int r = 0; r < NRPT; r++) {
        int Mk = NN + r;
        int rowsM = BB * Mk;
        int mtM64 = ceil_div(rowsM, 64);

        save_cls_kernel<<<ceil_div(BB * DD, 256), 256>>>(px, phist + (size_t)r * BB * DD);
        restore_patches_kernel<<<ceil_div(nXND, 256), 256>>>(px, x_in);
        build_mem8_kernel<<<ceil_div(BB * Mk * DD / 2, 256), 256>>>(pmem, px, phist, Mk);
        // repeat-start norm1 -> xn8 (within a repeat, fc2 fusion supplies it)
        ln_f8_kernel<<<ceil_div(rowsX, 8), 256>>>(px, pxn, norm1_w, norm1_b, rowsX);

        for (int l = 0; l < LL; l++) {
            const uint8_t* Wq = wqkv + (size_t)l * 3 * DD * DD;
            const uint8_t* Wk = Wq + (size_t)DD * DD;
            const uint8_t* Wv = Wq + (size_t)2 * DD * DD;
            const float* bq = qkv_b + (size_t)l * 3 * DD;
            const float* bk = bq + DD;
            const float* bv = bq + 2 * DD;
            int ln_next = (l + 1) % LL;

            // q8 = LN_qn(xn8 @ Wq^T + bq)
            gemm_ln_f8<<<dim3(1, mtX64, 1), 256, SMEM_LN>>>(
                pxn, Wq, bq, 0, 0, qn_w + l * DD, qn_b + l * DD, pq8, 0,
                rowsX, DD, DD, DD, 0, 0, 0, aQK, 0);
            // k8 = LN_kn(mem8 @ Wk^T + bk)
            gemm_ln_f8<<<dim3(1, mtM64, 1), 256, SMEM_LN>>>(
                pmem, Wk, bk, 0, 0, kn_w + l * DD, kn_b + l * DD, pk8, 0,
                rowsM, DD, DD, DD, 0, 0, 0, aMEMW, 0);
            // vT8 = (Wv @ mem^T + bv) * SC_V, zero-padded to MPAD
            mma_gemm_nt<<<dim3(MPAD / 128, 3, BB), 256, SMEM_G>>>(
                Wv, pmem, bv, pvT, DD, Mk, MPAD, DD, DD, DD, MPAD,
                0, (long)Mk * DD, (long)DD * MPAD, aMEMW, SC_V, 3);
            // attn8 = softmax(scale * q8 @ k8^T) * SC_ATTN (fused)
            gemm_sm_f8<<<dim3(1, ceil_div(NN, 32), BB), 256, SMEM_SM>>>(
                pq8, pk8, pattn, Mk, aSC);
            // pn8 = LN_an(attn8 @ vT8^T)
            gemm_ln_f8<<<dim3(1, ceil_div(NN, 64), BB), 256, SMEM_LN>>>(
                pattn, pvT, 0, 0, 0, an_w + l * DD, an_b + l * DD, ppn, 0,
                NN, MPAD, MPAD, MPAD,
                (long)NN * MPAD, (long)DD * MPAD, (long)NN * DD, aPV, 0);
            // x += (pn8 @ Wproj^T + pb)*ls1 ; xn8 = LN_norm2(x)
            gemm_ln_f8<<<dim3(1, mtX64, 1), 256, SMEM_LN>>>(
                ppn, wproj + (size_t)l * DD * DD, proj_b + l * DD, ls1 + l * DD, px,
                norm2_w + l * DD, norm2_b + l * DD, pxn, px,
                rowsX, DD, DD, DD, 0, 0, 0, aQK, 1);
            // h8 = gelu(xn8 @ Wfc1^T + b1) * SC_H
            mma_gemm_nt<<<dim3(HH / 128, ceil_div(rowsX, 128), 1), 256, SMEM_G>>>(
                pxn, wfc1 + (size_t)l * HH * DD, fc1_b + l * HH, ph,
                rowsX, HH, HH, DD, DD, DD, HH, 0, 0, 0, aFC1, SC_H, 1);
            // x += (h8 @ Wfc2^T + b2)*ls2 ; xn8 = LN_norm1[l+1](x)
            gemm_ln_f8<<<dim3(1, mtX64, 1), 256, SMEM_LN>>>(
                ph, wfc2 + (size_t)l * DD * HH, fc2_b + l * DD, ls2 + l * DD, px,
                norm1_w + ln_next * DD, norm1_b + ln_next * DD, pxn, px,
                rowsX, HH, HH, HH, 0, 0, 0, aFC2, 1);
        }
    }

    copy_kernel<<<ceil_div(nXND, 256), 256>>>(out, px, nXND);
}

// round 14
// speedup vs baseline: 3.2190x; 1.1377x over previous
#include <cuda_runtime.h>
#include <cuda_bf16.h>
#include <math.h>
#include <stdint.h>

#define BB 32
#define NN 577
#define DD 384
#define LL 12
#define NRPT 4
#define HH 1536
#define MMAX 580
#define MPAD 640

// ---------------- scratch ----------------
__device__ float g_x[BB * NN * DD];
__device__ float g_hist[NRPT * BB * DD];
__device__ __nv_bfloat16 g_qbf[BB * NN * DD];      // q / prod bf16 staging
__device__ __nv_bfloat16 g_kbf[BB * MMAX * DD];    // k bf16 staging (s1-serial)
__device__ __nv_bfloat16 g_scbf[(size_t)BB * NN * MPAD];
__device__ uint8_t g_mem8[BB * MMAX * DD];
__device__ uint8_t g_xn8[BB * NN * DD];
__device__ uint8_t g_q8[BB * NN * DD];
__device__ uint8_t g_pn8[BB * NN * DD];
__device__ uint8_t g_attn8[(size_t)BB * NN * MPAD];
__device__ uint8_t g_h8[(size_t)BB * NN * HH];
__device__ uint8_t g_k8L[(size_t)LL * BB * MMAX * DD];   // per-layer k8
__device__ uint8_t g_vT8L[(size_t)LL * BB * DD * MPAD];  // per-layer vT8
__device__ uint8_t g_wqkv8[LL * 3 * DD * DD];
__device__ uint8_t g_wproj8[LL * DD * DD];
__device__ uint8_t g_wfc18[LL * HH * DD];
__device__ uint8_t g_wfc28[LL * DD * HH];

// fp8 operand scales (powers of 2)
#define SC_W 32.0f
#define SC_LN 4.0f
#define SC_MEM 4.0f
#define SC_ATTN 16.0f
#define SC_V 8.0f
#define SC_H 16.0f

// ---------------- PTX helpers ----------------
__device__ __forceinline__ uint32_t smem_u32(const void* p) {
    uint32_t a;
    asm("{ .reg .u64 t; cvta.to.shared.u64 t, %1; cvt.u32.u64 %0, t; }" : "=r"(a) : "l"(p));
    return a;
}
__device__ __forceinline__ void cpasync16(uint32_t dst, const void* src, int srcsize) {
    asm volatile("cp.async.cg.shared.global [%0], [%1], 16, %2;" :: "r"(dst), "l"(src), "r"(srcsize));
}
__device__ __forceinline__ void cpcommit() { asm volatile("cp.async.commit_group;" ::: "memory"); }
__device__ __forceinline__ void cpwait1() { asm volatile("cp.async.wait_group 1;" ::: "memory"); }
__device__ __forceinline__ void cpwait0() { asm volatile("cp.async.wait_group 0;" ::: "memory"); }

__device__ __forceinline__ uint16_t pack_e4m3(float lo, float hi) {
    uint16_t r;
    asm("cvt.rn.satfinite.e4m3x2.f32 %0, %1, %2;" : "=h"(r) : "f"(hi), "f"(lo));
    return r;
}

#define LDSM4(r0, r1, r2, r3, a)                                                     \
    asm volatile("ldmatrix.sync.aligned.m8n8.x4.shared.b16 {%0,%1,%2,%3}, [%4];"     \
                 : "=r"(r0), "=r"(r1), "=r"(r2), "=r"(r3) : "r"(a))

#define MMAFP8(d, av, bv)                                                            \
    asm volatile("mma.sync.aligned.m16n8k32.row.col.f32.e4m3.e4m3.f32 "              \
                 "{%0,%1,%2,%3},{%4,%5,%6,%7},{%8,%9},{%0,%1,%2,%3};"                \
                 : "+f"((d)[0]), "+f"((d)[1]), "+f"((d)[2]), "+f"((d)[3])            \
                 : "r"((av)[0]), "r"((av)[1]), "r"((av)[2]), "r"((av)[3]),           \
                   "r"((bv)[0]), "r"((bv)[1]))

// smem: 3 stages x (A[128][128]fp8 16KB + B[128][128]fp8 16KB)
#define SM_A(s) ((s) * 32768)
#define SM_B(s) ((s) * 32768 + 16384)
#define SMEM_G (3 * 32768 + 1024)

__device__ __forceinline__ float gelu_exact(float v) {
    return 0.5f * v * (1.0f + erff(v * 0.70710678118654752f));
}

// ---------------- FP8 GEMM: C[M,*] = A[M,K](e4m3) @ W[N,K]^T(e4m3) + epilogue -------
// base = acc*alpha (+ bias)
// mode 1: fp8 out, v = gelu(base + bias[gn])*oscale          (Nvalid % 128 == 0)
// mode 2: f32 out, v = (base + bias[gn])*ls[gn] + res[..]    (Nvalid % 128 == 0)
// mode 3: fp8 out, v = (base + bias[gm])*oscale; zero-fill cols [Nvalid, Npad)
// mode 4: bf16 out, v = base (+ bias[gn]); stores pairs for all cols < Npad
__global__ void __launch_bounds__(256, 2)
mma_gemm_nt(const uint8_t* __restrict__ A, const uint8_t* __restrict__ W,
            const float* __restrict__ bias, const float* __restrict__ ls,
            const float* __restrict__ res, void* __restrict__ Cv,
            int Mrows, int Nvalid, int Npad, int K, int lda, int ldw, int ldc,
            long zA, long zW, long zC, float alpha, float oscale, int mode) {
    extern __shared__ char smraw[];
    uint32_t sbase = (smem_u32(smraw) + 1023u) & ~1023u;
    int tid = threadIdx.x, wid = tid >> 5, lid = tid & 31;
    int bz = blockIdx.z;
    A += (size_t)bz * zA;
    W += (size_t)bz * zW;
    const float* resp = res ? res + (size_t)bz * zC : (const float*)0;
    int m0 = blockIdx.y * 128, n0 = blockIdx.x * 128;
    int wm = wid & 3, wn = wid >> 2;

    float acc[2][8][4];
#pragma unroll
    for (int a = 0; a < 2; a++)
#pragma unroll
        for (int b = 0; b < 8; b++)
#pragma unroll
            for (int c = 0; c < 4; c++) acc[a][b][c] = 0.f;

    int nk = K >> 7;

#define LOADC_G(kc, s) do {                                                            \
    int _k0 = (kc) << 7;                                                               \
    _Pragma("unroll")                                                                  \
    for (int _i = 0; _i < 4; _i++) {                                                   \
        int _idx = tid + 256 * _i;                                                     \
        int _row = _idx >> 3, _g = _idx & 7;                                           \
        int _gm = m0 + _row;                                                           \
        int _pr = (_gm < Mrows) ? 16 : 0;                                              \
        const uint8_t* _src = A + (size_t)(_pr ? _gm : 0) * lda + _k0 + _g * 16;       \
        cpasync16(sbase + SM_A(s) + _row * 128 + (((_g ^ (_row & 7))) << 4), _src, _pr); \
    }                                                                                  \
    _Pragma("unroll")                                                                  \
    for (int _i = 0; _i < 4; _i++) {                                                   \
        int _idx = tid + 256 * _i;                                                     \
        int _row = _idx >> 3, _g = _idx & 7;                                           \
        int _gn = n0 + _row;                                                           \
        int _pr = (_gn < Nvalid) ? 16 : 0;                                             \
        const uint8_t* _src = W + (size_t)(_pr ? _gn : 0) * ldw + _k0 + _g * 16;       \
        cpasync16(sbase + SM_B(s) + _row * 128 + (((_g ^ (_row & 7))) << 4), _src, _pr); \
    }                                                                                  \
    cpcommit();                                                                        \
} while (0)

    LOADC_G(0, 0);
    if (nk > 1) LOADC_G(1, 1);
    int grp = lid >> 3, rin = lid & 7;
    int slot = 0;
    for (int i = 0; i < nk; i++) {
        if (i + 1 < nk) cpwait1(); else cpwait0();
        __syncthreads();
        if (i + 2 < nk) {
            int ns = slot + 2; if (ns >= 3) ns -= 3;
            LOADC_G(i + 2, ns);
        }
        int s = slot;
#pragma unroll
        for (int ks = 0; ks < 4; ks++) {
            uint32_t af[2][4], bf[8][2];
#pragma unroll
            for (int mt = 0; mt < 2; mt++) {
                int row = wm * 32 + mt * 16 + rin + (grp & 1) * 8;
                int kg = ks * 2 + (grp >> 1);
                uint32_t ad = sbase + SM_A(s) + row * 128 + ((kg ^ (row & 7)) << 4);
                LDSM4(af[mt][0], af[mt][1], af[mt][2], af[mt][3], ad);
            }
#pragma unroll
            for (int np = 0; np < 4; np++) {
                int row = wn * 64 + np * 16 + rin + (grp >> 1) * 8;
                int kg = ks * 2 + (grp & 1);
                uint32_t ad = sbase + SM_B(s) + row * 128 + ((kg ^ (row & 7)) << 4);
                LDSM4(bf[2 * np][0], bf[2 * np][1], bf[2 * np + 1][0], bf[2 * np + 1][1], ad);
            }
#pragma unroll
            for (int mt = 0; mt < 2; mt++)
#pragma unroll
                for (int nt = 0; nt < 8; nt++)
                    MMAFP8(acc[mt][nt], af[mt], bf[nt]);
        }
        slot++; if (slot >= 3) slot = 0;
    }

#pragma unroll
    for (int mt = 0; mt < 2; mt++) {
        int rbase = m0 + wm * 32 + mt * 16 + (lid >> 2);
#pragma unroll
        for (int nt = 0; nt < 8; nt++) {
            int c0 = n0 + wn * 64 + nt * 8 + (lid & 3) * 2;
#pragma unroll
            for (int half = 0; half < 2; half++) {
                int gm = rbase + half * 8;
                if (gm >= Mrows) continue;
                float a0 = acc[mt][nt][half * 2] * alpha;
                float a1 = acc[mt][nt][half * 2 + 1] * alpha;
                if (mode == 1) {
                    uint8_t* C = (uint8_t*)Cv + (size_t)bz * zC;
                    float v0 = gelu_exact(a0 + bias[c0]) * oscale;
                    float v1 = gelu_exact(a1 + bias[c0 + 1]) * oscale;
                    *(uint16_t*)(C + (size_t)gm * ldc + c0) = pack_e4m3(v0, v1);
                } else if (mode == 2) {
                    float* C = (float*)Cv + (size_t)bz * zC;
                    float2 r = *(const float2*)(resp + (size_t)gm * ldc + c0);
                    float2 v = make_float2((a0 + bias[c0]) * ls[c0] + r.x,
                                           (a1 + bias[c0 + 1]) * ls[c0 + 1] + r.y);
                    *(float2*)(C + (size_t)gm * ldc + c0) = v;
                } else if (mode == 3) {
                    uint8_t* C = (uint8_t*)Cv + (size_t)bz * zC;
                    float bb = bias ? bias[gm] : 0.f;
                    float v0 = (c0 < Nvalid) ? (a0 + bb) * oscale : 0.f;
                    float v1 = (c0 + 1 < Nvalid) ? (a1 + bb) * oscale : 0.f;
                    if (c0 + 1 < Npad)
                        *(uint16_t*)(C + (size_t)gm * ldc + c0) = pack_e4m3(v0, v1);
                } else {  // mode 4: bf16 out
                    __nv_bfloat16* C = (__nv_bfloat16*)Cv + (size_t)bz * zC;
                    float b0 = 0.f, b1 = 0.f;
                    if (bias) { b0 = bias[c0]; b1 = bias[c0 + 1]; }
                    __nv_bfloat162 v;
                    v.x = __float2bfloat16(a0 + b0);
                    v.y = __float2bfloat16(a1 + b1);
                    if (c0 + 1 < Npad)
                        *(__nv_bfloat162*)(C + (size_t)gm * ldc + c0) = v;
                }
            }
        }
    }
}

// ---------------- small kernels ----------------
__global__ void copy_kernel(float* __restrict__ dst, const float* __restrict__ src, int n) {
    int i = blockIdx.x * 256 + threadIdx.x;
    if (i < n) dst[i] = src[i];
}
__global__ void cvt_w8_kernel(uint8_t* __restrict__ dst, const float* __restrict__ src, int npair) {
    int i = blockIdx.x * 256 + threadIdx.x;
    if (i >= npair) return;
    float2 v = *(const float2*)(src + 2 * i);
    *(uint16_t*)(dst + 2 * i) = pack_e4m3(v.x * SC_W, v.y * SC_W);
}
__global__ void save_cls_kernel(const float* __restrict__ x, float* __restrict__ hist_r) {
    int i = blockIdx.x * 256 + threadIdx.x;
    if (i >= BB * DD) return;
    int b = i / DD, d = i % DD;
    hist_r[i] = x[(size_t)b * NN * DD + d];
}
__global__ void restore_patches_kernel(float* __restrict__ x, const float* __restrict__ x_in) {
    int i = blockIdx.x * 256 + threadIdx.x;
    if (i >= BB * NN * DD) return;
    int tok = (i / DD) % NN;
    if (tok != 0) x[i] = x_in[i];
}
__global__ void build_mem8_kernel(uint8_t* __restrict__ mem, const float* __restrict__ x,
                                  const float* __restrict__ hist, int Mk) {
    int i = blockIdx.x * 256 + threadIdx.x;
    int npair = BB * Mk * (DD / 2);
    if (i >= npair) return;
    int d2 = i % (DD / 2);
    int t = (i / (DD / 2)) % Mk;
    int b = i / ((DD / 2) * Mk);
    const float* src;
    if (t < NN) src = x + ((size_t)b * NN + t) * DD + 2 * d2;
    else        src = hist + ((size_t)(t - NN) * BB + b) * DD + 2 * d2;
    float2 v = *(const float2*)src;
    *(uint16_t*)(mem + ((size_t)b * Mk + t) * DD + 2 * d2) = pack_e4m3(v.x * SC_MEM, v.y * SC_MEM);
}

// layernorm f32 in -> e4m3 out (x SC_LN), 1 warp per row
__global__ void ln_f32_f8(const float* __restrict__ in, uint8_t* __restrict__ out,
                          const float* __restrict__ w, const float* __restrict__ b, int rows) {
    int row = blockIdx.x * 8 + (threadIdx.x >> 5);
    int lane = threadIdx.x & 31;
    if (row >= rows) return;
    const float2* p = (const float2*)(in + (size_t)row * DD);
    float2 v[6];
    float s = 0.f;
#pragma unroll
    for (int i = 0; i < 6; i++) { v[i] = p[lane + 32 * i]; s += v[i].x + v[i].y; }
#pragma unroll
    for (int o = 16; o; o >>= 1) s += __shfl_xor_sync(0xffffffffu, s, o);
    float mu = s * (1.0f / DD);
    float var = 0.f;
#pragma unroll
    for (int i = 0; i < 6; i++) {
        float dx = v[i].x - mu, dy = v[i].y - mu;
        var += dx * dx + dy * dy;
    }
#pragma unroll
    for (int o = 16; o; o >>= 1) var += __shfl_xor_sync(0xffffffffu, var, o);
    float inv = rsqrtf(var * (1.0f / DD) + 1e-6f);
    uint8_t* q = out + (size_t)row * DD;
    const float2* w2 = (const float2*)w;
    const float2* b2 = (const float2*)b;
#pragma unroll
    for (int i = 0; i < 6; i++) {
        int c = lane + 32 * i;
        float2 ww = w2[c], bb = b2[c];
        float o0 = ((v[i].x - mu) * inv * ww.x + bb.x) * SC_LN;
        float o1 = ((v[i].y - mu) * inv * ww.y + bb.y) * SC_LN;
        *(uint16_t*)(q + 2 * c) = pack_e4m3(o0, o1);
    }
}

// layernorm bf16 in -> e4m3 out (x SC_LN), 1 warp per row
__global__ void ln_bf_f8(const __nv_bfloat16* __restrict__ in, uint8_t* __restrict__ out,
                         const float* __restrict__ w, const float* __restrict__ b, int rows) {
    int row = blockIdx.x * 8 + (threadIdx.x >> 5);
    int lane = threadIdx.x & 31;
    if (row >= rows) return;
    const __nv_bfloat162* p = (const __nv_bfloat162*)(in + (size_t)row * DD);
    float2 v[6];
    float s = 0.f;
#pragma unroll
    for (int i = 0; i < 6; i++) {
        __nv_bfloat162 t = p[lane + 32 * i];
        v[i].x = __bfloat162float(t.x);
        v[i].y = __bfloat162float(t.y);
        s += v[i].x + v[i].y;
    }
#pragma unroll
    for (int o = 16; o; o >>= 1) s += __shfl_xor_sync(0xffffffffu, s, o);
    float mu = s * (1.0f / DD);
    float var = 0.f;
#pragma unroll
    for (int i = 0; i < 6; i++) {
        float dx = v[i].x - mu, dy = v[i].y - mu;
        var += dx * dx + dy * dy;
    }
#pragma unroll
    for (int o = 16; o; o >>= 1) var += __shfl_xor_sync(0xffffffffu, var, o);
    float inv = rsqrtf(var * (1.0f / DD) + 1e-6f);
    uint8_t* q = out + (size_t)row * DD;
    const float2* w2 = (const float2*)w;
    const float2* b2 = (const float2*)b;
#pragma unroll
    for (int i = 0; i < 6; i++) {
        int c = lane + 32 * i;
        float2 ww = w2[c], bb = b2[c];
        float o0 = ((v[i].x - mu) * inv * ww.x + bb.x) * SC_LN;
        float o1 = ((v[i].y - mu) * inv * ww.y + bb.y) * SC_LN;
        *(uint16_t*)(q + 2 * c) = pack_e4m3(o0, o1);
    }
}

// softmax: bf16 in (stride MPAD) -> e4m3 out x SC_ATTN (stride MPAD, zero-padded)
__global__ void softmax_bf_f8(const __nv_bfloat16* __restrict__ s, uint8_t* __restrict__ out,
                              int rows, int Mk) {
    int row = blockIdx.x * 8 + (threadIdx.x >> 5);
    int lane = threadIdx.x & 31;
    if (row >= rows) return;
    const __nv_bfloat162* p = (const __nv_bfloat162*)(s + (size_t)row * MPAD);
    float2 v[10];
    float mx = -1e30f;
#pragma unroll
    for (int i = 0; i < 10; i++) {
        int j = 2 * (lane + 32 * i);
        __nv_bfloat162 t = p[lane + 32 * i];
        v[i].x = (j < Mk) ? __bfloat162float(t.x) : -1e30f;
        v[i].y = (j + 1 < Mk) ? __bfloat162float(t.y) : -1e30f;
        mx = fmaxf(mx, fmaxf(v[i].x, v[i].y));
    }
#pragma unroll
    for (int o = 16; o; o >>= 1) mx = fmaxf(mx, __shfl_xor_sync(0xffffffffu, mx, o));
    float sum = 0.f;
#pragma unroll
    for (int i = 0; i < 10; i++) {
        v[i].x = __expf(v[i].x - mx);
        v[i].y = __expf(v[i].y - mx);
        sum += v[i].x + v[i].y;
    }
#pragma unroll
    for (int o = 16; o; o >>= 1) sum += __shfl_xor_sync(0xffffffffu, sum, o);
    float r = SC_ATTN / sum;
    uint8_t* q = out + (size_t)row * MPAD;
#pragma unroll
    for (int i = 0; i < 10; i++) {
        int j = 2 * (lane + 32 * i);
        float o0 = (j < Mk) ? v[i].x * r : 0.f;
        float o1 = (j + 1 < Mk) ? v[i].y * r : 0.f;
        *(uint16_t*)(q + j) = pack_e4m3(o0, o1);
    }
}

// ---------------- host orchestration ----------------
static inline int ceil_div(int a, int b) { return (a + b - 1) / b; }

extern "C" void kernel_launch(void* const* d_in, const int* in_sizes, int n_in,
                              void* d_out, int out_size) {
    const float* x_in    = (const float*)d_in[0];
    const float* norm1_w = (const float*)d_in[1];
    const float* norm1_b = (const float*)d_in[2];
    const float* qkv_w   = (const float*)d_in[3];
    const float* qkv_b   = (const float*)d_in[4];
    const float* qn_w    = (const float*)d_in[5];
    const float* qn_b    = (const float*)d_in[6];
    const float* kn_w    = (const float*)d_in[7];
    const float* kn_b    = (const float*)d_in[8];
    const float* an_w    = (const float*)d_in[9];
    const float* an_b    = (const float*)d_in[10];
    const float* proj_w  = (const float*)d_in[11];
    const float* proj_b  = (const float*)d_in[12];
    const float* ls1     = (const float*)d_in[13];
    const float* norm2_w = (const float*)d_in[14];
    const float* norm2_b = (const float*)d_in[15];
    const float* fc1_w   = (const float*)d_in[16];
    const float* fc1_b   = (const float*)d_in[17];
    const float* fc2_w   = (const float*)d_in[18];
    const float* fc2_b   = (const float*)d_in[19];
    const float* ls2     = (const float*)d_in[20];
    float* out = (float*)d_out;

    cudaFuncSetAttribute(mma_gemm_nt, cudaFuncAttributeMaxDynamicSharedMemorySize, SMEM_G);

    // streams/events for fork-join inside graph capture (created once, host objects only)
    static cudaStream_t s1 = 0, s2 = 0;
    static cudaEvent_t e_mem = 0, ek[LL], ev[LL];
    static int init_done = 0;
    if (!init_done) {
        cudaStreamCreateWithFlags(&s1, cudaStreamNonBlocking);
        cudaStreamCreateWithFlags(&s2, cudaStreamNonBlocking);
        cudaEventCreateWithFlags(&e_mem, cudaEventDisableTiming);
        for (int l = 0; l < LL; l++) {
            cudaEventCreateWithFlags(&ek[l], cudaEventDisableTiming);
            cudaEventCreateWithFlags(&ev[l], cudaEventDisableTiming);
        }
        init_done = 1;
    }

    float *px, *phist;
    __nv_bfloat16 *pqbf, *pkbf, *pscbf;
    uint8_t *pmem, *pxn, *pq8, *ppn, *pattn, *ph, *pk8L, *pvTL;
    uint8_t *wqkv, *wproj, *wfc1, *wfc2;
    cudaGetSymbolAddress((void**)&px, g_x);
    cudaGetSymbolAddress((void**)&phist, g_hist);
    cudaGetSymbolAddress((void**)&pqbf, g_qbf);
    cudaGetSymbolAddress((void**)&pkbf, g_kbf);
    cudaGetSymbolAddress((void**)&pscbf, g_scbf);
    cudaGetSymbolAddress((void**)&pmem, g_mem8);
    cudaGetSymbolAddress((void**)&pxn, g_xn8);
    cudaGetSymbolAddress((void**)&pq8, g_q8);
    cudaGetSymbolAddress((void**)&ppn, g_pn8);
    cudaGetSymbolAddress((void**)&pattn, g_attn8);
    cudaGetSymbolAddress((void**)&ph, g_h8);
    cudaGetSymbolAddress((void**)&pk8L, g_k8L);
    cudaGetSymbolAddress((void**)&pvTL, g_vT8L);
    cudaGetSymbolAddress((void**)&wqkv, g_wqkv8);
    cudaGetSymbolAddress((void**)&wproj, g_wproj8);
    cudaGetSymbolAddress((void**)&wfc1, g_wfc18);
    cudaGetSymbolAddress((void**)&wfc2, g_wfc28);

    const float scale = 1.0f / sqrtf((float)DD);
    const int nXND = BB * NN * DD;
    const int rowsX = BB * NN;

    const float aQK   = 1.0f / (SC_LN * SC_W);
    const float aMEMW = 1.0f / (SC_MEM * SC_W);
    const float aSC   = scale / (SC_LN * SC_LN);
    const float aPV   = 1.0f / (SC_ATTN * SC_V);
    const float aFC1  = 1.0f / (SC_LN * SC_W);
    const float aFC2  = 1.0f / (SC_H * SC_W);

    {
        int n1 = LL * 3 * DD * DD / 2;
        cvt_w8_kernel<<<ceil_div(n1, 256), 256>>>(wqkv, qkv_w, n1);
        int n2 = LL * DD * DD / 2;
        cvt_w8_kernel<<<ceil_div(n2, 256), 256>>>(wproj, proj_w, n2);
        int n3 = LL * HH * DD / 2;
        cvt_w8_kernel<<<ceil_div(n3, 256), 256>>>(wfc1, fc1_w, n3);
        cvt_w8_kernel<<<ceil_div(n3, 256), 256>>>(wfc2, fc2_w, n3);
    }

    copy_kernel<<<ceil_div(nXND, 256), 256>>>(px, x_in, nXND);

    for (int r = 0; r < NRPT; r++) {
        int Mk = NN + r;
        int rowsM = BB * Mk;
        int mtX = ceil_div(rowsX, 128);
        int mtM = ceil_div(rowsM, 128);
        int ntMk = ceil_div(Mk, 128);
        long zK8 = (long)BB * MMAX * DD;   // per-layer k8 block
        long zVT = (long)BB * DD * MPAD;   // per-layer vT8 block

        save_cls_kernel<<<ceil_div(BB * DD, 256), 256>>>(px, phist + (size_t)r * BB * DD);
        restore_patches_kernel<<<ceil_div(nXND, 256), 256>>>(px, x_in);
        build_mem8_kernel<<<ceil_div(BB * Mk * DD / 2, 256), 256>>>(pmem, px, phist, Mk);
        cudaEventRecord(e_mem, 0);
        cudaStreamWaitEvent(s1, e_mem, 0);
        cudaStreamWaitEvent(s2, e_mem, 0);

        // hoisted side work: all layers' k8 (s1) and vT8 (s2) depend only on mem
        for (int l = 0; l < LL; l++) {
            const uint8_t* Wk = wqkv + (size_t)l * 3 * DD * DD + (size_t)DD * DD;
            const float* bk = qkv_b + (size_t)l * 3 * DD + DD;
            mma_gemm_nt<<<dim3(3, mtM, 1), 256, SMEM_G, s1>>>(
                pmem, Wk, bk, 0, 0, pkbf, rowsM, DD, DD, DD, DD, DD, DD,
                0, 0, 0, aMEMW, 1.f, 4);
            ln_bf_f8<<<ceil_div(rowsM, 8), 256, 0, s1>>>(
                pkbf, pk8L + (size_t)l * zK8, kn_w + l * DD, kn_b + l * DD, rowsM);
            cudaEventRecord(ek[l], s1);
        }
        for (int l = 0; l < LL; l++) {
            const uint8_t* Wv = wqkv + (size_t)l * 3 * DD * DD + (size_t)2 * DD * DD;
            const float* bv = qkv_b + (size_t)l * 3 * DD + 2 * DD;
            mma_gemm_nt<<<dim3(MPAD / 128, 3, BB), 256, SMEM_G, s2>>>(
                Wv, pmem, bv, 0, 0, pvTL + (size_t)l * zVT, DD, Mk, MPAD, DD, DD, DD, MPAD,
                0, (long)Mk * DD, (long)DD * MPAD, aMEMW, SC_V, 3);
            cudaEventRecord(ev[l], s2);
        }

        // main chain on default stream
        for (int l = 0; l < LL; l++) {
            const uint8_t* Wq = wqkv + (size_t)l * 3 * DD * DD;
            const float* bq = qkv_b + (size_t)l * 3 * DD;

            // norm1 -> xn8
            ln_f32_f8<<<ceil_div(rowsX, 8), 256>>>(px, pxn, norm1_w + l * DD, norm1_b + l * DD, rowsX);
            // q(bf16) = xn8 @ Wq^T + bq
            mma_gemm_nt<<<dim3(3, mtX, 1), 256, SMEM_G>>>(
                pxn, Wq, bq, 0, 0, pqbf, rowsX, DD, DD, DD, DD, DD, DD, 0, 0, 0, aQK, 1.f, 4);
            // q8 = LN_qn(q)
            ln_bf_f8<<<ceil_div(rowsX, 8), 256>>>(pqbf, pq8, qn_w + l * DD, qn_b + l * DD, rowsX);
            // scores(bf16) = scale * q8 @ k8^T
            cudaStreamWaitEvent(0, ek[l], 0);
            mma_gemm_nt<<<dim3(ntMk, ceil_div(NN, 128), BB), 256, SMEM_G>>>(
                pq8, pk8L + (size_t)l * zK8, 0, 0, 0, pscbf, NN, Mk, MPAD, DD, DD, DD, MPAD,
                (long)NN * DD, (long)Mk * DD, (long)NN * MPAD, aSC, 1.f, 4);
            // attn8 = softmax
            softmax_bf_f8<<<ceil_div(BB * NN, 8), 256>>>(pscbf, pattn, BB * NN, Mk);
            // prod(bf16) = attn8 @ vT8^T
            cudaStreamWaitEvent(0, ev[l], 0);
            mma_gemm_nt<<<dim3(3, ceil_div(NN, 128), BB), 256, SMEM_G>>>(
                pattn, pvTL + (size_t)l * zVT, 0, 0, 0, pqbf, NN, DD, DD, MPAD, MPAD, MPAD, DD,
                (long)NN * MPAD, (long)DD * MPAD, (long)NN * DD, aPV, 1.f, 4);
            // pn8 = LN_an(prod)
            ln_bf_f8<<<ceil_div(rowsX, 8), 256>>>(pqbf, ppn, an_w + l * DD, an_b + l * DD, rowsX);
            // x += (pn8 @ Wproj^T + pb) * ls1
            mma_gemm_nt<<<dim3(3, mtX, 1), 256, SMEM_G>>>(
                ppn, wproj + (size_t)l * DD * DD, proj_b + l * DD, ls1 + l * DD, px, px,
                rowsX, DD, DD, DD, DD, DD, DD, 0, 0, 0, aQK, 1.f, 2);
            // norm2 -> xn8
            ln_f32_f8<<<ceil_div(rowsX, 8), 256>>>(px, pxn, norm2_w + l * DD, norm2_b + l * DD, rowsX);
            // h8 = gelu(xn8 @ Wfc1^T + b1) * SC_H
            mma_gemm_nt<<<dim3(HH / 128, mtX, 1), 256, SMEM_G>>>(
                pxn, wfc1 + (size_t)l * HH * DD, fc1_b + l * HH, 0, 0, ph,
                rowsX, HH, HH, DD, DD, DD, HH, 0, 0, 0, aFC1, SC_H, 1);
            // x += (h8 @ Wfc2^T + b2) * ls2
            mma_gemm_nt<<<dim3(3, mtX, 1), 256, SMEM_G>>>(
                ph, wfc2 + (size_t)l * DD * HH, fc2_b + l * DD, ls2 + l * DD, px, px,
                rowsX, DD, DD, HH, HH, HH, DD, 0, 0, 0, aFC2, 1.f, 2);
        }
    }

    copy_kernel<<<ceil_div(nXND, 256), 256>>>(out, px, nXND);
}